// round 11
// baseline (speedup 1.0000x reference)
#include <cuda_runtime.h>
#include <math_constants.h>

#define NM 1024
#define HGT 256
#define WID 256
#define HW 65536
#define NPART 4
#define NFB 64          // blocks in fused nms+fixup kernel
#define FIX_PARTS 16    // 16KB zero-fill units per missed mask (1024 thr x float4)

#define MASK_THR 0.0f
#define STAB_OFF 1.0f
#define IOU_THR 0.88f
#define STAB_THR 0.95f
#define NMS_THR 0.7f
#define FULLM 0xffffffffu

// Scratch (static device globals -- no runtime allocation)
__device__ int2 g_cnt[NPART * NM];        // (hi, lo) partials
__device__ int4 g_bxp[NPART * NM];        // (L, R, T, B) partials
__device__ unsigned g_supmask[NM * 32];   // fallback only (M > 352); value-identical across blocks

// ---------------------------------------------------------------------------
// Row sweep, templated on candidate status. Candidates (iou > IOU_THR) get a
// speculative sigmoid(v)*iou written to out -- exactly the final value if the
// mask survives NMS. Non-candidates can never be kept, so they get zeros.
// ---------------------------------------------------------------------------
template<bool CAND>
__device__ __forceinline__ void sweep(const float* __restrict__ base,
                                      float4* __restrict__ ob,
                                      int y0, int lane, float gi,
                                      int& hi, int& lo, int& top, int& bot,
                                      unsigned& colmask) {
    #pragma unroll 4
    for (int r = 0; r < 8; r++) {
        const int y = y0 + r;
        const float4* row = reinterpret_cast<const float4*>(base + (size_t)y * WID);
        float4 a = __ldcs(&row[lane]);
        float4 b = __ldcs(&row[lane + 32]);

        float4 oa, obv;
        if (CAND) {
            oa.x = __fdividef(gi, 1.f + __expf(-a.x));
            oa.y = __fdividef(gi, 1.f + __expf(-a.y));
            oa.z = __fdividef(gi, 1.f + __expf(-a.z));
            oa.w = __fdividef(gi, 1.f + __expf(-a.w));
            obv.x = __fdividef(gi, 1.f + __expf(-b.x));
            obv.y = __fdividef(gi, 1.f + __expf(-b.y));
            obv.z = __fdividef(gi, 1.f + __expf(-b.z));
            obv.w = __fdividef(gi, 1.f + __expf(-b.w));
        } else {
            oa  = make_float4(0.f, 0.f, 0.f, 0.f);
            obv = make_float4(0.f, 0.f, 0.f, 0.f);
        }
        __stcs(&ob[(size_t)y * (WID / 4) + lane], oa);
        __stcs(&ob[(size_t)y * (WID / 4) + lane + 32], obv);

        unsigned rm = 0;
        float va[8] = {a.x, a.y, a.z, a.w, b.x, b.y, b.z, b.w};
        #pragma unroll
        for (int c = 0; c < 8; c++) {
            float f = va[c];
            hi += (f > (MASK_THR + STAB_OFF)) ? 1 : 0;
            lo += (f > (MASK_THR - STAB_OFF)) ? 1 : 0;
            rm |= (f > MASK_THR) ? (1u << c) : 0u;
        }
        if (rm) {
            top = min(top, y);
            bot = y;                 // rows ascend -> last positive row wins
            colmask |= rm;
        }
    }
}

// ---------------------------------------------------------------------------
// Kernel 1: per-mask stats fused with speculative output write.
// ---------------------------------------------------------------------------
__global__ __launch_bounds__(256) void stats_spec_kernel(const float* __restrict__ logits,
                                                         const float* __restrict__ iou,
                                                         float* __restrict__ out) {
    const int part = blockIdx.x;
    const int n = blockIdx.y;
    const int warp = threadIdx.x >> 5;
    const int lane = threadIdx.x & 31;
    const size_t mbase = (size_t)n * HW;
    const float* base = logits + mbase;
    float4* ob = reinterpret_cast<float4*>(out + mbase);
    const int y0 = part * 64 + warp * 8;
    const float gi = iou[n];

    int hi = 0, lo = 0;
    int top = HGT, bot = -1;
    unsigned colmask = 0;

    if (gi > IOU_THR)
        sweep<true>(base, ob, y0, lane, gi, hi, lo, top, bot, colmask);
    else
        sweep<false>(base, ob, y0, lane, gi, hi, lo, top, bot, colmask);

    int left = WID, right = -1;
    unsigned lowm = colmask & 0xFu, highm = colmask >> 4;
    if (lowm)  left = lane * 4 + (__ffs(lowm) - 1);
    else if (highm) left = lane * 4 + 128 + (__ffs(highm) - 1);
    if (highm) right = lane * 4 + 128 + (31 - __clz(highm));
    else if (lowm) right = lane * 4 + (31 - __clz(lowm));

    #pragma unroll
    for (int o = 16; o; o >>= 1) {
        hi   += __shfl_xor_sync(FULLM, hi, o);
        lo   += __shfl_xor_sync(FULLM, lo, o);
        left  = min(left,  __shfl_xor_sync(FULLM, left, o));
        right = max(right, __shfl_xor_sync(FULLM, right, o));
        top   = min(top,   __shfl_xor_sync(FULLM, top, o));
        bot   = max(bot,   __shfl_xor_sync(FULLM, bot, o));
    }

    __shared__ int s[8][6];
    if (lane == 0) {
        s[warp][0] = hi; s[warp][1] = lo;
        s[warp][2] = left; s[warp][3] = right;
        s[warp][4] = top; s[warp][5] = bot;
    }
    __syncthreads();
    if (threadIdx.x == 0) {
        int Hi = 0, Lo = 0, L = WID, R = -1, T = HGT, B = -1;
        #pragma unroll
        for (int w = 0; w < 8; w++) {
            Hi += s[w][0]; Lo += s[w][1];
            L = min(L, s[w][2]); R = max(R, s[w][3]);
            T = min(T, s[w][4]); B = max(B, s[w][5]);
        }
        const int o = part * NM + n;
        g_cnt[o] = make_int2(Hi, Lo);
        g_bxp[o] = make_int4(L, R, T, B);
    }
}

// ---------------------------------------------------------------------------
// Kernel 2 (fused): fast NMS + fixup. NFB blocks x 1024 threads; every block
// redundantly computes the IDENTICAL NMS (all steps deterministic: ballot/
// scan compaction, rank sort, warp-per-row matrix, single-thread greedy --
// no atomics anywhere), so no inter-block communication is needed. Block 0
// writes the keep/boxes tail; all blocks zero-fill their blockIdx-strided
// share of mis-speculated-mask sub-tiles.
// ---------------------------------------------------------------------------
__global__ __launch_bounds__(1024) void nms_fix_kernel(const float* __restrict__ iou,
                                                       float* __restrict__ out) {
    const int tid = threadIdx.x;
    const int lane = tid & 31;
    const int wid = tid >> 5;
    float* out_tail = out + (size_t)NM * HW;

    __shared__ float s_cs[NM];            // compacted scores
    __shared__ float4 s_sbx[NM];          // boxes in SORTED order
    __shared__ int s_sorted[NM];          // sorted -> original id (fallback paths)
    __shared__ union {
        uint4 row[128];                   // fast path: M<=128 suppression rows
        unsigned sup[4096];               // fallback matrix (M in (128,352])
    } mx;
    __shared__ unsigned s_keepw[4];       // fast-path keep bits by rank
    __shared__ unsigned char s_keep[NM];  // fallback keep by original id
    __shared__ int s_miss[NM];
    __shared__ int s_wcnt[32];
    __shared__ int s_mcnt[32];

    float myiou = iou[tid];

    // Combine the 4 stats partials (vectorized).
    int Hi = 0, Lo = 0, L = WID, R = -1, T = HGT, B = -1;
    #pragma unroll
    for (int p = 0; p < NPART; p++) {
        const int o = p * NM + tid;
        int2 cl = g_cnt[o];
        int4 bx = g_bxp[o];
        Hi += cl.x; Lo += cl.y;
        L = min(L, bx.x); R = max(R, bx.y);
        T = min(T, bx.z); B = max(B, bx.w);
    }
    bool nonempty = (B >= 0);
    float4 bf = nonempty
        ? make_float4((float)L, (float)T, (float)R, (float)B)
        : make_float4(0.f, 0.f, 0.f, 0.f);

    float stab = (float)Hi / fmaxf((float)Lo, 1.0f);
    bool cand = (myiou > IOU_THR);
    bool valid = cand && (stab >= STAB_THR);
    s_keep[tid] = 0;

    // Compaction: stable (tid-order) pack of valid entries; prefix via shfl scan.
    unsigned bal = __ballot_sync(FULLM, valid);
    if (lane == 0) s_wcnt[wid] = __popc(bal);
    __syncthreads();
    int v = s_wcnt[lane];
    int sc = v;
    #pragma unroll
    for (int o = 1; o < 32; o <<= 1) {
        int t = __shfl_up_sync(FULLM, sc, o);
        if (lane >= o) sc += t;
    }
    const int M = __shfl_sync(FULLM, sc, 31);
    const int wbase = __shfl_sync(FULLM, sc - v, wid);
    int c = -1;
    if (valid) {
        c = wbase + __popc(bal & ((1u << lane) - 1u));
        s_cs[c] = myiou;
    }
    __syncthreads();

    // Rank among valid entries: score desc, ties -> lower original index.
    int r = -1;
    if (valid) {
        r = 0;
        const float si = myiou;
        #pragma unroll 4
        for (int j = 0; j < M; j++) {
            float sj = s_cs[j];
            r += ((sj > si) || (sj == si && j < c)) ? 1 : 0;
        }
        s_sorted[r] = tid;
        s_sbx[r] = bf;
    }
    __syncthreads();

    if (M > 0 && M <= 128) {
        // Suppression rows: warp w -> rows w, w+32, ...; lane l covers
        // columns l, l+32, l+64, l+96.
        for (int i = wid; i < M; i += 32) {
            float4 bi = s_sbx[i];
            float areaA = fmaxf(bi.z - bi.x, 0.f) * fmaxf(bi.w - bi.y, 0.f);
            unsigned w[4];
            #pragma unroll
            for (int k = 0; k < 4; k++) {
                int j = lane + 32 * k;
                bool bit = false;
                if (j < M) {
                    float4 bj = s_sbx[j];
                    float areaB = fmaxf(bj.z - bj.x, 0.f) * fmaxf(bj.w - bj.y, 0.f);
                    float ix = fmaxf(fminf(bi.z, bj.z) - fmaxf(bi.x, bj.x), 0.f);
                    float iy = fmaxf(fminf(bi.w, bj.w) - fmaxf(bi.y, bj.y), 0.f);
                    float inter = ix * iy;
                    float iouv = inter / fmaxf(areaA + areaB - inter, 1e-6f);
                    bit = (iouv > NMS_THR);
                }
                w[k] = __ballot_sync(FULLM, bit);
            }
            if (lane == 0) mx.row[i] = make_uint4(w[0], w[1], w[2], w[3]);
        }
        __syncthreads();

        // Single-thread greedy: removal mask in 4 registers, one uint4 LDS
        // per kept box. No shuffles, no per-step branch sync.
        if (tid == 0) {
            unsigned rem0 = 0, rem1 = 0, rem2 = 0, rem3 = 0;
            unsigned kw0 = 0, kw1 = 0, kw2 = 0, kw3 = 0;
            for (int i = 0; i < M; i++) {
                unsigned rw = (i < 32) ? rem0 : (i < 64) ? rem1 : (i < 96) ? rem2 : rem3;
                if (!((rw >> (i & 31)) & 1u)) {
                    if (i < 32) kw0 |= 1u << i;
                    else if (i < 64) kw1 |= 1u << (i - 32);
                    else if (i < 96) kw2 |= 1u << (i - 64);
                    else kw3 |= 1u << (i - 96);
                    uint4 rr = mx.row[i];
                    rem0 |= rr.x; rem1 |= rr.y; rem2 |= rr.z; rem3 |= rr.w;
                }
            }
            s_keepw[0] = kw0; s_keepw[1] = kw1; s_keepw[2] = kw2; s_keepw[3] = kw3;
        }
    } else if (M > 0 && M <= 352) {
        // Shared suppression matrix + single-warp bitmask greedy.
        const int nwords = (M + 31) >> 5;
        if (tid < nwords * 32) {
            float4 cb = (tid < M) ? s_sbx[tid] : make_float4(0.f, 0.f, 0.f, 0.f);
            float areaB = fmaxf(cb.z - cb.x, 0.f) * fmaxf(cb.w - cb.y, 0.f);
            for (int i = 0; i < M; i++) {
                float4 ib = s_sbx[i];
                float areaA = fmaxf(ib.z - ib.x, 0.f) * fmaxf(ib.w - ib.y, 0.f);
                float ix = fmaxf(fminf(ib.z, cb.z) - fmaxf(ib.x, cb.x), 0.f);
                float iy = fmaxf(fminf(ib.w, cb.w) - fmaxf(ib.y, cb.y), 0.f);
                float inter = ix * iy;
                float iouv = inter / fmaxf(areaA + areaB - inter, 1e-6f);
                bool bit = (tid < M) && (iouv > NMS_THR);
                unsigned bl = __ballot_sync(FULLM, bit);
                if (lane == 0) mx.sup[i * nwords + wid] = bl;
            }
        }
        __syncthreads();
        if (tid < 32) {
            unsigned removed = 0;
            for (int i = 0; i < M; i++) {
                unsigned w = __shfl_sync(FULLM, removed, i >> 5);
                if (!((w >> (i & 31)) & 1u)) {
                    removed |= (tid < nwords) ? mx.sup[i * nwords + tid] : 0u;
                    if (tid == 0) s_keep[s_sorted[i]] = 1;
                }
            }
        }
    } else if (M > 0) {
        // Global matrix fallback (rarely hit); identical writes across blocks.
        float4 mb = (tid < M) ? s_sbx[tid] : make_float4(0.f, 0.f, 0.f, 0.f);
        float areaB = fmaxf(mb.z - mb.x, 0.f) * fmaxf(mb.w - mb.y, 0.f);
        for (int i = 0; i < M; i++) {
            float4 ib = s_sbx[i];
            float areaA = fmaxf(ib.z - ib.x, 0.f) * fmaxf(ib.w - ib.y, 0.f);
            float ix = fmaxf(fminf(ib.z, mb.z) - fmaxf(ib.x, mb.x), 0.f);
            float iy = fmaxf(fminf(ib.w, mb.w) - fmaxf(ib.y, mb.y), 0.f);
            float inter = ix * iy;
            float iouv = inter / fmaxf(areaA + areaB - inter, 1e-6f);
            bool bit = (tid < M) && (iouv > NMS_THR);
            unsigned bl = __ballot_sync(FULLM, bit);
            if (lane == 0) g_supmask[i * 32 + wid] = bl;
        }
        __syncthreads();
        if (tid < 32) {
            unsigned removed = 0;
            for (int i = 0; i < M; i++) {
                unsigned w = __shfl_sync(FULLM, removed, i >> 5);
                if (!((w >> (i & 31)) & 1u)) {
                    removed |= g_supmask[i * 32 + tid];
                    if (tid == 0) s_keep[s_sorted[i]] = 1;
                }
            }
        }
    }
    __syncthreads();

    bool kp;
    if (M <= 128)
        kp = valid && ((s_keepw[r >> 5] >> (r & 31)) & 1u);
    else
        kp = (s_keep[tid] != 0);

    if (blockIdx.x == 0) {
        out_tail[tid] = kp ? 1.f : 0.f;              // keep[N] as float
        float* ob = out_tail + NM + (size_t)tid * 4; // boxes [N,4]
        ob[0] = bf.x; ob[1] = bf.y; ob[2] = bf.z; ob[3] = bf.w;
    }

    // Deterministic (tid-stable) miss-list compaction -- identical in every
    // block, so the blockIdx-strided fixup partition is consistent with no
    // inter-block communication.
    bool miss = cand && !kp;
    unsigned mbal = __ballot_sync(FULLM, miss);
    if (lane == 0) s_mcnt[wid] = __popc(mbal);
    __syncthreads();
    int mv = s_mcnt[lane];
    int msc = mv;
    #pragma unroll
    for (int o = 1; o < 32; o <<= 1) {
        int t = __shfl_up_sync(FULLM, msc, o);
        if (lane >= o) msc += t;
    }
    const int cnt = __shfl_sync(FULLM, msc, 31);
    const int mbase2 = __shfl_sync(FULLM, msc - mv, wid);
    if (miss)
        s_miss[mbase2 + __popc(mbal & ((1u << lane) - 1u))] = tid;
    __syncthreads();

    // Fixup: zero the mis-speculated masks. Unit = 16KB (1024 thr x float4).
    const float4 z = make_float4(0.f, 0.f, 0.f, 0.f);
    const int units = cnt * FIX_PARTS;
    for (int uu = blockIdx.x; uu < units; uu += NFB) {
        const int n = s_miss[uu >> 4];
        const int p = uu & (FIX_PARTS - 1);
        float4* o4 = reinterpret_cast<float4*>(out + (size_t)n * HW + (size_t)p * (HW / FIX_PARTS));
        __stcs(&o4[tid], z);
    }
}

extern "C" void kernel_launch(void* const* d_in, const int* in_sizes, int n_in,
                              void* d_out, int out_size) {
    const float* logits = (const float*)d_in[0];
    const float* iou = (const float*)d_in[1];
    if (n_in >= 2 && in_sizes[0] == NM && in_sizes[1] == NM * HW) {
        // Defensive against input-order swap.
        logits = (const float*)d_in[1];
        iou = (const float*)d_in[0];
    }
    float* out = (float*)d_out;

    dim3 sgrid(NPART, NM);
    stats_spec_kernel<<<sgrid, 256>>>(logits, iou, out);
    nms_fix_kernel<<<NFB, 1024>>>(iou, out);
}

// round 14
// speedup vs baseline: 1.1463x; 1.1463x over previous
#include <cuda_runtime.h>
#include <math_constants.h>

#define NM 1024
#define HGT 256
#define WID 256
#define HW 65536
#define NPART 4
#define FIX_SLOTS 64
#define FIX_PARTS 16

#define MASK_THR 0.0f
#define STAB_OFF 1.0f
#define IOU_THR 0.88f
#define STAB_THR 0.95f
#define NMS_THR 0.7f
#define FULLM 0xffffffffu

// Scratch (static device globals -- no runtime allocation)
__device__ int2 g_cnt[NPART * NM];        // (hi, lo) partials
__device__ int4 g_bxp[NPART * NM];        // (L, R, T, B) partials
__device__ int g_misscnt;                 // # mis-speculated candidate masks
__device__ int g_miss[NM];                // their ids
__device__ unsigned g_supmask[NM * 32];   // fallback path only (M > 352)

// ---------------------------------------------------------------------------
// Row sweep, templated on candidate status. Candidates (iou > IOU_THR) get a
// speculative sigmoid(v)*iou written to out -- exactly the final value if the
// mask survives NMS. Non-candidates can never be kept, so they get zeros.
// ---------------------------------------------------------------------------
template<bool CAND>
__device__ __forceinline__ void sweep(const float* __restrict__ base,
                                      float4* __restrict__ ob,
                                      int y0, int lane, float gi,
                                      int& hi, int& lo, int& top, int& bot,
                                      unsigned& colmask) {
    #pragma unroll 4
    for (int r = 0; r < 8; r++) {
        const int y = y0 + r;
        const float4* row = reinterpret_cast<const float4*>(base + (size_t)y * WID);
        float4 a = __ldcs(&row[lane]);
        float4 b = __ldcs(&row[lane + 32]);

        float4 oa, obv;
        if (CAND) {
            oa.x = __fdividef(gi, 1.f + __expf(-a.x));
            oa.y = __fdividef(gi, 1.f + __expf(-a.y));
            oa.z = __fdividef(gi, 1.f + __expf(-a.z));
            oa.w = __fdividef(gi, 1.f + __expf(-a.w));
            obv.x = __fdividef(gi, 1.f + __expf(-b.x));
            obv.y = __fdividef(gi, 1.f + __expf(-b.y));
            obv.z = __fdividef(gi, 1.f + __expf(-b.z));
            obv.w = __fdividef(gi, 1.f + __expf(-b.w));
        } else {
            oa  = make_float4(0.f, 0.f, 0.f, 0.f);
            obv = make_float4(0.f, 0.f, 0.f, 0.f);
        }
        __stcs(&ob[(size_t)y * (WID / 4) + lane], oa);
        __stcs(&ob[(size_t)y * (WID / 4) + lane + 32], obv);

        unsigned rm = 0;
        float va[8] = {a.x, a.y, a.z, a.w, b.x, b.y, b.z, b.w};
        #pragma unroll
        for (int c = 0; c < 8; c++) {
            float f = va[c];
            hi += (f > (MASK_THR + STAB_OFF)) ? 1 : 0;
            lo += (f > (MASK_THR - STAB_OFF)) ? 1 : 0;
            rm |= (f > MASK_THR) ? (1u << c) : 0u;
        }
        if (rm) {
            top = min(top, y);
            bot = y;                 // rows ascend -> last positive row wins
            colmask |= rm;
        }
    }
}

// ---------------------------------------------------------------------------
// Kernel 1: per-mask stats fused with speculative output write.
// ---------------------------------------------------------------------------
__global__ __launch_bounds__(256) void stats_spec_kernel(const float* __restrict__ logits,
                                                         const float* __restrict__ iou,
                                                         float* __restrict__ out) {
    // Let the dependent nms launch begin its prologue early (PDL). Its
    // cudaGridDependencySynchronize() still waits for this whole grid.
    cudaTriggerProgrammaticLaunchCompletion();

    const int part = blockIdx.x;
    const int n = blockIdx.y;
    const int warp = threadIdx.x >> 5;
    const int lane = threadIdx.x & 31;
    const size_t mbase = (size_t)n * HW;
    const float* base = logits + mbase;
    float4* ob = reinterpret_cast<float4*>(out + mbase);
    const int y0 = part * 64 + warp * 8;
    const float gi = iou[n];

    int hi = 0, lo = 0;
    int top = HGT, bot = -1;
    unsigned colmask = 0;

    if (gi > IOU_THR)
        sweep<true>(base, ob, y0, lane, gi, hi, lo, top, bot, colmask);
    else
        sweep<false>(base, ob, y0, lane, gi, hi, lo, top, bot, colmask);

    int left = WID, right = -1;
    unsigned lowm = colmask & 0xFu, highm = colmask >> 4;
    if (lowm)  left = lane * 4 + (__ffs(lowm) - 1);
    else if (highm) left = lane * 4 + 128 + (__ffs(highm) - 1);
    if (highm) right = lane * 4 + 128 + (31 - __clz(highm));
    else if (lowm) right = lane * 4 + (31 - __clz(lowm));

    #pragma unroll
    for (int o = 16; o; o >>= 1) {
        hi   += __shfl_xor_sync(FULLM, hi, o);
        lo   += __shfl_xor_sync(FULLM, lo, o);
        left  = min(left,  __shfl_xor_sync(FULLM, left, o));
        right = max(right, __shfl_xor_sync(FULLM, right, o));
        top   = min(top,   __shfl_xor_sync(FULLM, top, o));
        bot   = max(bot,   __shfl_xor_sync(FULLM, bot, o));
    }

    __shared__ int s[8][6];
    if (lane == 0) {
        s[warp][0] = hi; s[warp][1] = lo;
        s[warp][2] = left; s[warp][3] = right;
        s[warp][4] = top; s[warp][5] = bot;
    }
    __syncthreads();
    if (threadIdx.x == 0) {
        int Hi = 0, Lo = 0, L = WID, R = -1, T = HGT, B = -1;
        #pragma unroll
        for (int w = 0; w < 8; w++) {
            Hi += s[w][0]; Lo += s[w][1];
            L = min(L, s[w][2]); R = max(R, s[w][3]);
            T = min(T, s[w][4]); B = max(B, s[w][5]);
        }
        const int o = part * NM + n;
        g_cnt[o] = make_int2(Hi, Lo);
        g_bxp[o] = make_int4(L, R, T, B);
    }
}

// ---------------------------------------------------------------------------
// Kernel 2: NMS (round-10 proven fast path). Warp-scan prefixes, direct
// sorted-slot scatter, warp-per-row suppression matrix, single-thread greedy.
// ---------------------------------------------------------------------------
__global__ __launch_bounds__(1024) void nms_kernel(const float* __restrict__ iou,
                                                   float* __restrict__ out_tail) {
    const int tid = threadIdx.x;
    const int lane = tid & 31;
    const int wid = tid >> 5;

    __shared__ float s_cs[NM];            // compacted scores
    __shared__ float4 s_sbx[NM];          // boxes in SORTED order
    __shared__ int s_sorted[NM];          // sorted -> original id (fallback paths)
    __shared__ union {
        uint4 row[128];                   // fast path: M<=128 suppression rows
        unsigned sup[4096];               // fallback matrix (M in (128,352])
    } mx;
    __shared__ unsigned s_keepw[4];       // fast-path keep bits by rank
    __shared__ unsigned char s_keep[NM];  // fallback keep by original id
    __shared__ int s_wcnt[32];
    __shared__ int s_mcnt[32];

    float myiou = iou[tid];               // input array: safe to read pre-sync
    s_keep[tid] = 0;

    // Wait for stats grid's memory before touching the partials.
    cudaGridDependencySynchronize();
    cudaTriggerProgrammaticLaunchCompletion();

    // Combine the 4 stats partials (vectorized).
    int Hi = 0, Lo = 0, L = WID, R = -1, T = HGT, B = -1;
    #pragma unroll
    for (int p = 0; p < NPART; p++) {
        const int o = p * NM + tid;
        int2 cl = g_cnt[o];
        int4 bx = g_bxp[o];
        Hi += cl.x; Lo += cl.y;
        L = min(L, bx.x); R = max(R, bx.y);
        T = min(T, bx.z); B = max(B, bx.w);
    }
    bool nonempty = (B >= 0);
    float4 bf = nonempty
        ? make_float4((float)L, (float)T, (float)R, (float)B)
        : make_float4(0.f, 0.f, 0.f, 0.f);

    float stab = (float)Hi / fmaxf((float)Lo, 1.0f);
    bool cand = (myiou > IOU_THR);
    bool valid = cand && (stab >= STAB_THR);

    // Compaction: stable (tid-order) pack of valid entries; prefix via shfl scan.
    unsigned bal = __ballot_sync(FULLM, valid);
    if (lane == 0) s_wcnt[wid] = __popc(bal);
    __syncthreads();
    int v = s_wcnt[lane];
    int sc = v;
    #pragma unroll
    for (int o = 1; o < 32; o <<= 1) {
        int t = __shfl_up_sync(FULLM, sc, o);
        if (lane >= o) sc += t;
    }
    const int M = __shfl_sync(FULLM, sc, 31);
    const int wbase = __shfl_sync(FULLM, sc - v, wid);
    int c = -1;
    if (valid) {
        c = wbase + __popc(bal & ((1u << lane) - 1u));
        s_cs[c] = myiou;
    }
    __syncthreads();

    // Rank among valid entries: score desc, ties -> lower original index.
    int r = -1;
    if (valid) {
        r = 0;
        const float si = myiou;
        #pragma unroll 4
        for (int j = 0; j < M; j++) {
            float sj = s_cs[j];
            r += ((sj > si) || (sj == si && j < c)) ? 1 : 0;
        }
        s_sorted[r] = tid;
        s_sbx[r] = bf;
    }
    __syncthreads();

    if (M > 0 && M <= 128) {
        // Suppression rows: warp w -> rows w, w+32, ...; lane l covers
        // columns l, l+32, l+64, l+96.
        for (int i = wid; i < M; i += 32) {
            float4 bi = s_sbx[i];
            float areaA = fmaxf(bi.z - bi.x, 0.f) * fmaxf(bi.w - bi.y, 0.f);
            unsigned w[4];
            #pragma unroll
            for (int k = 0; k < 4; k++) {
                int j = lane + 32 * k;
                bool bit = false;
                if (j < M) {
                    float4 bj = s_sbx[j];
                    float areaB = fmaxf(bj.z - bj.x, 0.f) * fmaxf(bj.w - bj.y, 0.f);
                    float ix = fmaxf(fminf(bi.z, bj.z) - fmaxf(bi.x, bj.x), 0.f);
                    float iy = fmaxf(fminf(bi.w, bj.w) - fmaxf(bi.y, bj.y), 0.f);
                    float inter = ix * iy;
                    float iouv = inter / fmaxf(areaA + areaB - inter, 1e-6f);
                    bit = (iouv > NMS_THR);
                }
                w[k] = __ballot_sync(FULLM, bit);
            }
            if (lane == 0) mx.row[i] = make_uint4(w[0], w[1], w[2], w[3]);
        }
        __syncthreads();

        // Single-thread greedy: removal mask in 4 registers, one uint4 LDS
        // per kept box. No shuffles, no per-step branch sync.
        if (tid == 0) {
            unsigned rem0 = 0, rem1 = 0, rem2 = 0, rem3 = 0;
            unsigned kw0 = 0, kw1 = 0, kw2 = 0, kw3 = 0;
            for (int i = 0; i < M; i++) {
                unsigned rw = (i < 32) ? rem0 : (i < 64) ? rem1 : (i < 96) ? rem2 : rem3;
                if (!((rw >> (i & 31)) & 1u)) {
                    if (i < 32) kw0 |= 1u << i;
                    else if (i < 64) kw1 |= 1u << (i - 32);
                    else if (i < 96) kw2 |= 1u << (i - 64);
                    else kw3 |= 1u << (i - 96);
                    uint4 rr = mx.row[i];
                    rem0 |= rr.x; rem1 |= rr.y; rem2 |= rr.z; rem3 |= rr.w;
                }
            }
            s_keepw[0] = kw0; s_keepw[1] = kw1; s_keepw[2] = kw2; s_keepw[3] = kw3;
        }
    } else if (M > 0 && M <= 352) {
        // Shared suppression matrix + single-warp bitmask greedy.
        const int nwords = (M + 31) >> 5;
        if (tid < nwords * 32) {
            float4 cb = (tid < M) ? s_sbx[tid] : make_float4(0.f, 0.f, 0.f, 0.f);
            float areaB = fmaxf(cb.z - cb.x, 0.f) * fmaxf(cb.w - cb.y, 0.f);
            for (int i = 0; i < M; i++) {
                float4 ib = s_sbx[i];
                float areaA = fmaxf(ib.z - ib.x, 0.f) * fmaxf(ib.w - ib.y, 0.f);
                float ix = fmaxf(fminf(ib.z, cb.z) - fmaxf(ib.x, cb.x), 0.f);
                float iy = fmaxf(fminf(ib.w, cb.w) - fmaxf(ib.y, cb.y), 0.f);
                float inter = ix * iy;
                float iouv = inter / fmaxf(areaA + areaB - inter, 1e-6f);
                bool bit = (tid < M) && (iouv > NMS_THR);
                unsigned bl = __ballot_sync(FULLM, bit);
                if (lane == 0) mx.sup[i * nwords + wid] = bl;
            }
        }
        __syncthreads();
        if (tid < 32) {
            unsigned removed = 0;
            for (int i = 0; i < M; i++) {
                unsigned w = __shfl_sync(FULLM, removed, i >> 5);
                if (!((w >> (i & 31)) & 1u)) {
                    removed |= (tid < nwords) ? mx.sup[i * nwords + tid] : 0u;
                    if (tid == 0) s_keep[s_sorted[i]] = 1;
                }
            }
        }
    } else if (M > 0) {
        // Global matrix fallback (rarely hit).
        float4 mb = (tid < M) ? s_sbx[tid] : make_float4(0.f, 0.f, 0.f, 0.f);
        float areaB = fmaxf(mb.z - mb.x, 0.f) * fmaxf(mb.w - mb.y, 0.f);
        for (int i = 0; i < M; i++) {
            float4 ib = s_sbx[i];
            float areaA = fmaxf(ib.z - ib.x, 0.f) * fmaxf(ib.w - ib.y, 0.f);
            float ix = fmaxf(fminf(ib.z, mb.z) - fmaxf(ib.x, mb.x), 0.f);
            float iy = fmaxf(fminf(ib.w, mb.w) - fmaxf(ib.y, mb.y), 0.f);
            float inter = ix * iy;
            float iouv = inter / fmaxf(areaA + areaB - inter, 1e-6f);
            bool bit = (tid < M) && (iouv > NMS_THR);
            unsigned bl = __ballot_sync(FULLM, bit);
            if (lane == 0) g_supmask[i * 32 + wid] = bl;
        }
        __syncthreads();
        if (tid < 32) {
            unsigned removed = 0;
            for (int i = 0; i < M; i++) {
                unsigned w = __shfl_sync(FULLM, removed, i >> 5);
                if (!((w >> (i & 31)) & 1u)) {
                    removed |= g_supmask[i * 32 + tid];
                    if (tid == 0) s_keep[s_sorted[i]] = 1;
                }
            }
        }
    }
    __syncthreads();

    bool kp;
    if (M <= 128)
        kp = valid && ((s_keepw[r >> 5] >> (r & 31)) & 1u);
    else
        kp = (s_keep[tid] != 0);

    out_tail[tid] = kp ? 1.f : 0.f;                               // keep[N]
    reinterpret_cast<float4*>(out_tail + NM)[tid] = bf;           // boxes [N,4]

    // Deterministic (tid-stable) miss-list compaction for the fixup kernel.
    bool miss = cand && !kp;
    unsigned mbal = __ballot_sync(FULLM, miss);
    if (lane == 0) s_mcnt[wid] = __popc(mbal);
    __syncthreads();
    int mv = s_mcnt[lane];
    int msc = mv;
    #pragma unroll
    for (int o = 1; o < 32; o <<= 1) {
        int t = __shfl_up_sync(FULLM, msc, o);
        if (lane >= o) msc += t;
    }
    const int cnt = __shfl_sync(FULLM, msc, 31);
    const int mbase2 = __shfl_sync(FULLM, msc - mv, wid);
    if (miss)
        g_miss[mbase2 + __popc(mbal & ((1u << lane) - 1u))] = tid;
    if (tid == 0) g_misscnt = cnt;
}

// ---------------------------------------------------------------------------
// Kernel 3: fixup -- zero-fill the few candidate masks that NMS rejected.
// ---------------------------------------------------------------------------
__global__ __launch_bounds__(256) void fixup_kernel(float* __restrict__ out) {
    // Wait for nms's miss list (and, transitively, stats' writes to out).
    cudaGridDependencySynchronize();

    const int cnt = g_misscnt;
    const int tid = threadIdx.x;
    const float4 z = make_float4(0.f, 0.f, 0.f, 0.f);
    for (int j = blockIdx.y; j < cnt; j += FIX_SLOTS) {
        const int n = g_miss[j];
        const size_t base = (size_t)n * HW + (size_t)blockIdx.x * (HW / FIX_PARTS);
        float4* o4 = reinterpret_cast<float4*>(out + base);
        #pragma unroll
        for (int k = 0; k < HW / FIX_PARTS / 4 / 256; k++)
            __stcs(&o4[tid + 256 * k], z);
    }
}

extern "C" void kernel_launch(void* const* d_in, const int* in_sizes, int n_in,
                              void* d_out, int out_size) {
    const float* logits = (const float*)d_in[0];
    const float* iou = (const float*)d_in[1];
    if (n_in >= 2 && in_sizes[0] == NM && in_sizes[1] == NM * HW) {
        // Defensive against input-order swap.
        logits = (const float*)d_in[1];
        iou = (const float*)d_in[0];
    }
    float* out = (float*)d_out;

    // Kernel 1: plain launch.
    dim3 sgrid(NPART, NM);
    stats_spec_kernel<<<sgrid, 256>>>(logits, iou, out);

    // Kernel 2 + 3: PDL launches -- prelaunch overlaps the predecessor's tail;
    // cudaGridDependencySynchronize() inside preserves ordering.
    cudaLaunchAttribute attr;
    attr.id = cudaLaunchAttributeProgrammaticStreamSerialization;
    attr.val.programmaticStreamSerializationAllowed = 1;

    {
        cudaLaunchConfig_t cfg = {};
        cfg.gridDim = dim3(1, 1, 1);
        cfg.blockDim = dim3(1024, 1, 1);
        cfg.attrs = &attr;
        cfg.numAttrs = 1;
        const float* a0 = iou;
        float* a1 = out + (size_t)NM * HW;
        cudaLaunchKernelEx(&cfg, nms_kernel, a0, a1);
    }
    {
        cudaLaunchConfig_t cfg = {};
        cfg.gridDim = dim3(FIX_PARTS, FIX_SLOTS, 1);
        cfg.blockDim = dim3(256, 1, 1);
        cfg.attrs = &attr;
        cfg.numAttrs = 1;
        cudaLaunchKernelEx(&cfg, fixup_kernel, out);
    }
}